// round 3
// baseline (speedup 1.0000x reference)
#include <cuda_runtime.h>

#define NN 50000
#define NE 800000
#define ETOT (NE + NN)   // 850000 edges incl. self loops
#define C 64

// ---------------- scratch (no allocations allowed) ----------------
__device__ __align__(16) float d_z[NN * C];
__device__ __align__(16) float d_h[NN * C];
__device__ __align__(16) float d_acc[NN * C];
__device__ float d_es[NN];
__device__ float d_ed[NN];
__device__ unsigned d_mk[NN];
__device__ float d_den[NN];
__device__ float d_e[ETOT];

// monotone float<->uint encoding so atomicMax(unsigned) implements float max
__device__ __forceinline__ unsigned fenc(float f) {
    unsigned u = __float_as_uint(f);
    return (u & 0x80000000u) ? ~u : (u | 0x80000000u);
}
__device__ __forceinline__ float fdec(unsigned k) {
    return __uint_as_float((k & 0x80000000u) ? (k & 0x7fffffffu) : ~k);
}

__global__ void k_init() {
    int t = blockIdx.x * blockDim.x + threadIdx.x;
    if (t < NN * C) d_acc[t] = 0.f;
    if (t < NN) { d_mk[t] = 0u; d_den[t] = 0.f; }
}

// z = h @ W ; e_src = z . a_src ; e_dst = z . a_dst
// 256 threads = 4 nodes x 64 output cols. NN % 4 == 0 so no tail guard needed.
template <int CIN>
__global__ void k_gemm(const float* __restrict__ hin,
                       const float* __restrict__ W,
                       const float* __restrict__ as_,
                       const float* __restrict__ ad_) {
    const float* h = hin ? hin : d_h;
    int local = threadIdx.x >> 6;   // node within block (0..3)
    int j     = threadIdx.x & 63;   // output column
    int node  = blockIdx.x * 4 + local;

    __shared__ float sh[4][CIN];
    __shared__ float sred[8][2];

    for (int k = j; k < CIN; k += 64) sh[local][k] = h[node * CIN + k];
    __syncthreads();

    float acc = 0.f;
#pragma unroll
    for (int k = 0; k < CIN; k++) acc = fmaf(sh[local][k], W[k * C + j], acc);
    d_z[node * C + j] = acc;

    float ps = acc * as_[j];
    float pd = acc * ad_[j];
#pragma unroll
    for (int off = 16; off; off >>= 1) {
        ps += __shfl_down_sync(0xffffffffu, ps, off);
        pd += __shfl_down_sync(0xffffffffu, pd, off);
    }
    int w = threadIdx.x >> 5;
    if ((threadIdx.x & 31) == 0) { sred[w][0] = ps; sred[w][1] = pd; }
    __syncthreads();
    if (j == 0) {
        d_es[node] = sred[2 * local][0] + sred[2 * local + 1][0];
        d_ed[node] = sred[2 * local][1] + sred[2 * local + 1][1];
    }
}

// edge_index arrives as int32 (harness dtype universe: float32/int32/bf16).
// Layout [2, E] row-major: src = ei[i], dst = ei[NE + i]. Self-loops appended.
__device__ __forceinline__ void edge_sd(const int* __restrict__ ei,
                                        int i, int& s, int& d) {
    if (i < NE) { s = ei[i]; d = ei[NE + i]; }
    else        { s = i - NE; d = s; }
}

__global__ void k_edge_max(const int* __restrict__ ei) {
    int i = blockIdx.x * blockDim.x + threadIdx.x;
    if (i >= ETOT) return;
    int s, d; edge_sd(ei, i, s, d);
    float e = d_es[s] + d_ed[d];
    e = e > 0.f ? e : 0.2f * e;          // leaky_relu(0.2) on attention logit
    d_e[i] = e;
    atomicMax(&d_mk[d], fenc(e));
}

__global__ void k_edge_exp(const int* __restrict__ ei) {
    int i = blockIdx.x * blockDim.x + threadIdx.x;
    if (i >= ETOT) return;
    int s, d; edge_sd(ei, i, s, d);
    float ex = expf(d_e[i] - fdec(d_mk[d]));
    d_e[i] = ex;                          // reuse buffer: e -> exp(e - m)
    atomicAdd(&d_den[d], ex);
}

// 16 threads per edge; each thread handles one float4 chunk of the 64-wide row.
__global__ void k_edge_agg(const int* __restrict__ ei,
                           float* __restrict__ out_alpha) {
    int t = blockIdx.x * blockDim.x + threadIdx.x;
    int i = t >> 4;
    if (i >= ETOT) return;
    int c = t & 15;
    int s, d; edge_sd(ei, i, s, d);
    float alpha = d_e[i] / (d_den[d] + 1e-16f);
    if (out_alpha && c == 0) out_alpha[i] = alpha;
    float4 z = *(const float4*)(d_z + s * C + c * 4);
    float* base = d_acc + d * C + c * 4;
    atomicAdd(base + 0, alpha * z.x);
    atomicAdd(base + 1, alpha * z.y);
    atomicAdd(base + 2, alpha * z.z);
    atomicAdd(base + 3, alpha * z.w);
}

__global__ void k_final(const float* __restrict__ b, float* __restrict__ out) {
    int t = blockIdx.x * blockDim.x + threadIdx.x;
    if (t >= NN * C) return;
    float v = d_acc[t] + b[t & 63];
    v = v > 0.f ? v : 0.01f * v;          // inter-layer leaky_relu(0.01)
    if (out) out[t] = v; else d_h[t] = v;
}

// ei output region: [2, E+N] row-major, cast to float
__global__ void k_write_ei(const int* __restrict__ ei,
                           float* __restrict__ out) {
    int t = blockIdx.x * blockDim.x + threadIdx.x;
    if (t >= 2 * ETOT) return;
    int row = t / ETOT, k = t - row * ETOT;
    int v = (k < NE) ? ei[row * NE + k] : (k - NE);
    out[t] = (float)v;
}

extern "C" void kernel_launch(void* const* d_in, const int* in_sizes, int n_in,
                              void* d_out, int out_size) {
    const float* x  = (const float*)d_in[0];
    const int*   ei = (const int*)d_in[1];
    const float* W[3]   = {(const float*)d_in[2], (const float*)d_in[6],  (const float*)d_in[10]};
    const float* as_[3] = {(const float*)d_in[3], (const float*)d_in[7],  (const float*)d_in[11]};
    const float* ad_[3] = {(const float*)d_in[4], (const float*)d_in[8],  (const float*)d_in[12]};
    const float* b[3]   = {(const float*)d_in[5], (const float*)d_in[9],  (const float*)d_in[13]};

    float* out       = (float*)d_out;
    bool   tuple_out = (out_size > NN * C);
    float* out_ei    = tuple_out ? out + NN * C : nullptr;
    float* out_alpha = tuple_out ? out + NN * C + 2 * ETOT : nullptr;

    if (tuple_out)
        k_write_ei<<<(2 * ETOT + 255) / 256, 256>>>(ei, out_ei);

    for (int l = 0; l < 3; l++) {
        k_init<<<(NN * C + 255) / 256, 256>>>();
        if (l == 0) k_gemm<128><<<NN / 4, 256>>>(x, W[0], as_[0], ad_[0]);
        else        k_gemm<64><<<NN / 4, 256>>>(nullptr, W[l], as_[l], ad_[l]);
        k_edge_max<<<(ETOT + 255) / 256, 256>>>(ei);
        k_edge_exp<<<(ETOT + 255) / 256, 256>>>(ei);
        k_edge_agg<<<(ETOT * 16 + 255) / 256, 256>>>(ei, (l == 2) ? out_alpha : nullptr);
        k_final<<<(NN * C + 255) / 256, 256>>>(b[l], (l == 2) ? out : nullptr);
    }
}

// round 4
// speedup vs baseline: 1.6458x; 1.6458x over previous
#include <cuda_runtime.h>

#define NN 50000
#define NE 800000
#define ETOT (NE + NN)   // 850000 edges incl. self loops
#define C 64

// ---------------- scratch (no allocations allowed) ----------------
__device__ __align__(16) float d_z[NN * C];
__device__ __align__(16) float d_h[NN * C];
__device__ float d_es[NN];
__device__ float d_ed[NN];
// CSR (dst-major), rebuilt each launch (graph replays must redo all work)
__device__ int d_cnt[NN];
__device__ int d_off[NN + 1];
__device__ int d_pos[NN];
__device__ int d_csr_src[ETOT];
__device__ int d_csr_eid[ETOT];

// edge_index arrives as int32, [2, E] row-major. Self-loops appended logically.
__device__ __forceinline__ void edge_sd(const int* __restrict__ ei,
                                        int i, int& s, int& d) {
    if (i < NE) { s = ei[i]; d = ei[NE + i]; }
    else        { s = i - NE; d = s; }
}

// ---------------- CSR build ----------------
__global__ void k_zero_cnt() {
    int t = blockIdx.x * blockDim.x + threadIdx.x;
    if (t < NN) d_cnt[t] = 0;
}

__global__ void k_hist(const int* __restrict__ ei) {
    int i = blockIdx.x * blockDim.x + threadIdx.x;
    if (i >= ETOT) return;
    int s, d; edge_sd(ei, i, s, d);
    atomicAdd(&d_cnt[d], 1);
}

#define SCAN_T 1024
__global__ void k_scan() {
    __shared__ int part[SCAN_T];
    int t = threadIdx.x;
    const int CH = (NN + SCAN_T - 1) / SCAN_T;   // 49
    int beg = t * CH;
    int end = beg + CH < NN ? beg + CH : NN;
    int s = 0;
    for (int i = beg; i < end; i++) s += d_cnt[i];
    part[t] = s;
    __syncthreads();
    for (int off = 1; off < SCAN_T; off <<= 1) {
        int v = (t >= off) ? part[t - off] : 0;
        __syncthreads();
        part[t] += v;
        __syncthreads();
    }
    int run = part[t] - s;   // exclusive base for this chunk
    for (int i = beg; i < end; i++) {
        int c = d_cnt[i];
        d_off[i] = run;
        d_pos[i] = run;
        run += c;
    }
    if (t == SCAN_T - 1) d_off[NN] = ETOT;
}

__global__ void k_scatter(const int* __restrict__ ei) {
    int i = blockIdx.x * blockDim.x + threadIdx.x;
    if (i >= ETOT) return;
    int s, d; edge_sd(ei, i, s, d);
    int p = atomicAdd(&d_pos[d], 1);
    d_csr_src[p] = s;
    d_csr_eid[p] = i;
}

// ---------------- per-layer compute ----------------
// z = h @ W ; e_src = z . a_src ; e_dst = z . a_dst
// 256 threads = 4 nodes x 64 output cols. NN % 4 == 0.
template <int CIN>
__global__ void k_gemm(const float* __restrict__ hin,
                       const float* __restrict__ W,
                       const float* __restrict__ as_,
                       const float* __restrict__ ad_) {
    const float* h = hin ? hin : d_h;
    int local = threadIdx.x >> 6;
    int j     = threadIdx.x & 63;
    int node  = blockIdx.x * 4 + local;

    __shared__ float sh[4][CIN];
    __shared__ float sred[8][2];

    for (int k = j; k < CIN; k += 64) sh[local][k] = h[node * CIN + k];
    __syncthreads();

    float acc = 0.f;
#pragma unroll
    for (int k = 0; k < CIN; k++) acc = fmaf(sh[local][k], W[k * C + j], acc);
    d_z[node * C + j] = acc;

    float ps = acc * as_[j];
    float pd = acc * ad_[j];
#pragma unroll
    for (int off = 16; off; off >>= 1) {
        ps += __shfl_down_sync(0xffffffffu, ps, off);
        pd += __shfl_down_sync(0xffffffffu, pd, off);
    }
    int w = threadIdx.x >> 5;
    if ((threadIdx.x & 31) == 0) { sred[w][0] = ps; sred[w][1] = pd; }
    __syncthreads();
    if (j == 0) {
        d_es[node] = sred[2 * local][0] + sred[2 * local + 1][0];
        d_ed[node] = sred[2 * local][1] + sred[2 * local + 1][1];
    }
}

// Warp per dst node: segment max -> exp-sum -> alpha-weighted gather of z.
// Atomic-free; h written once, fused bias + leaky_relu(0.01).
template <int WRITE_OUT>
__global__ void k_node(const float* __restrict__ b,
                       float* __restrict__ outh,
                       float* __restrict__ out_alpha) {
    int w = (blockIdx.x * blockDim.x + threadIdx.x) >> 5;
    if (w >= NN) return;
    int lane = threadIdx.x & 31;
    int beg = d_off[w], end = d_off[w + 1];
    float edv = d_ed[w];

    float m = -1e30f;
    for (int e = beg + lane; e < end; e += 32) {
        float v = d_es[d_csr_src[e]] + edv;
        v = v > 0.f ? v : 0.2f * v;
        m = fmaxf(m, v);
    }
#pragma unroll
    for (int o = 16; o; o >>= 1) m = fmaxf(m, __shfl_xor_sync(0xffffffffu, m, o));

    float den = 0.f;
    for (int e = beg + lane; e < end; e += 32) {
        float v = d_es[d_csr_src[e]] + edv;
        v = v > 0.f ? v : 0.2f * v;
        den += __expf(v - m);
    }
#pragma unroll
    for (int o = 16; o; o >>= 1) den += __shfl_xor_sync(0xffffffffu, den, o);
    float inv = 1.f / (den + 1e-16f);

    float a0 = 0.f, a1 = 0.f;
    for (int e = beg; e < end; e++) {
        int s = d_csr_src[e];
        float v = d_es[s] + edv;
        v = v > 0.f ? v : 0.2f * v;
        float alpha = __expf(v - m) * inv;
        a0 = fmaf(alpha, d_z[s * C + lane], a0);
        a1 = fmaf(alpha, d_z[s * C + 32 + lane], a1);
        if (WRITE_OUT && lane == 0) out_alpha[d_csr_eid[e]] = alpha;
    }
    float o0 = a0 + b[lane];      o0 = o0 > 0.f ? o0 : 0.01f * o0;
    float o1 = a1 + b[lane + 32]; o1 = o1 > 0.f ? o1 : 0.01f * o1;
    if (WRITE_OUT) { outh[w * C + lane] = o0; outh[w * C + 32 + lane] = o1; }
    else           { d_h[w * C + lane] = o0;  d_h[w * C + 32 + lane] = o1; }
}

// ei output region: [2, E+N] row-major, cast to float
__global__ void k_write_ei(const int* __restrict__ ei,
                           float* __restrict__ out) {
    int t = blockIdx.x * blockDim.x + threadIdx.x;
    if (t >= 2 * ETOT) return;
    int row = t / ETOT, k = t - row * ETOT;
    int v = (k < NE) ? ei[row * NE + k] : (k - NE);
    out[t] = (float)v;
}

extern "C" void kernel_launch(void* const* d_in, const int* in_sizes, int n_in,
                              void* d_out, int out_size) {
    const float* x  = (const float*)d_in[0];
    const int*   ei = (const int*)d_in[1];
    const float* W[3]   = {(const float*)d_in[2], (const float*)d_in[6],  (const float*)d_in[10]};
    const float* as_[3] = {(const float*)d_in[3], (const float*)d_in[7],  (const float*)d_in[11]};
    const float* ad_[3] = {(const float*)d_in[4], (const float*)d_in[8],  (const float*)d_in[12]};
    const float* b[3]   = {(const float*)d_in[5], (const float*)d_in[9],  (const float*)d_in[13]};

    float* out       = (float*)d_out;
    bool   tuple_out = (out_size > NN * C);
    float* out_ei    = tuple_out ? out + NN * C : nullptr;
    float* out_alpha = tuple_out ? out + NN * C + 2 * ETOT : nullptr;

    if (tuple_out)
        k_write_ei<<<(2 * ETOT + 255) / 256, 256>>>(ei, out_ei);

    // CSR build (once per launch; graph replay re-executes it)
    k_zero_cnt<<<(NN + 255) / 256, 256>>>();
    k_hist<<<(ETOT + 255) / 256, 256>>>(ei);
    k_scan<<<1, SCAN_T>>>();
    k_scatter<<<(ETOT + 255) / 256, 256>>>(ei);

    for (int l = 0; l < 3; l++) {
        if (l == 0) k_gemm<128><<<NN / 4, 256>>>(x, W[0], as_[0], ad_[0]);
        else        k_gemm<64><<<NN / 4, 256>>>(nullptr, W[l], as_[l], ad_[l]);
        if (l == 2) k_node<1><<<(NN * 32 + 255) / 256, 256>>>(b[l], out, out_alpha);
        else        k_node<0><<<(NN * 32 + 255) / 256, 256>>>(b[l], nullptr, nullptr);
    }
}

// round 5
// speedup vs baseline: 2.0324x; 1.2349x over previous
#include <cuda_runtime.h>

#define NN 50000
#define NE 800000
#define ETOT (NE + NN)   // 850000 edges incl. self loops
#define C 64

#define SCAN_BLK 1024                       // elements per scan block
#define NSB ((NN + SCAN_BLK - 1) / SCAN_BLK)  // 49 scan blocks

// ---------------- scratch (no allocations allowed) ----------------
__device__ __align__(16) float d_z[NN * C];
__device__ __align__(16) float d_h[NN * C];
__device__ float d_es[NN];
__device__ float d_ed[NN];
// CSR (dst-major), rebuilt each launch
__device__ int d_cnt[NN];
__device__ int d_off[NN + 1];
__device__ int d_pos[NN];
__device__ int d_bsum[NSB];
__device__ int d_csr_src[ETOT];
__device__ int d_csr_eid[ETOT];

// edge_index arrives as int32, [2, E] row-major. Self-loops appended logically.
__device__ __forceinline__ void edge_sd(const int* __restrict__ ei,
                                        int i, int& s, int& d) {
    if (i < NE) { s = ei[i]; d = ei[NE + i]; }
    else        { s = i - NE; d = s; }
}

// ---------------- CSR build ----------------
__global__ void k_zero_cnt() {
    int t = blockIdx.x * blockDim.x + threadIdx.x;
    if (t < NN) d_cnt[t] = 0;
}

__global__ void k_hist(const int* __restrict__ ei) {
    int i = blockIdx.x * blockDim.x + threadIdx.x;
    if (i >= ETOT) return;
    int s, d; edge_sd(ei, i, s, d);
    atomicAdd(&d_cnt[d], 1);
}

// Pass 1: per-block exclusive offsets (local) + block totals.
// 256 threads x 4 elements = 1024 elements per block.
__global__ void k_scan1() {
    int t = threadIdx.x, lane = t & 31, warp = t >> 5;
    int base = blockIdx.x * SCAN_BLK + t * 4;
    int c0 = (base + 0 < NN) ? d_cnt[base + 0] : 0;
    int c1 = (base + 1 < NN) ? d_cnt[base + 1] : 0;
    int c2 = (base + 2 < NN) ? d_cnt[base + 2] : 0;
    int c3 = (base + 3 < NN) ? d_cnt[base + 3] : 0;
    int s = c0 + c1 + c2 + c3;

    int inc = s;
#pragma unroll
    for (int o = 1; o < 32; o <<= 1) {
        int x = __shfl_up_sync(0xffffffffu, inc, o);
        if (lane >= o) inc += x;
    }
    __shared__ int wsum[8];
    if (lane == 31) wsum[warp] = inc;
    __syncthreads();
    if (t < 8) {
        int x = wsum[t];
        int ix = x;
#pragma unroll
        for (int o = 1; o < 8; o <<= 1) {
            int y = __shfl_up_sync(0xffu, ix, o);
            if (t >= o) ix += y;
        }
        wsum[t] = ix - x;                 // exclusive warp base
        if (t == 7) d_bsum[blockIdx.x] = ix;  // block total
    }
    __syncthreads();
    int excl = wsum[warp] + inc - s;      // exclusive offset of element 0
    if (base + 0 < NN) d_off[base + 0] = excl;
    if (base + 1 < NN) d_off[base + 1] = excl + c0;
    if (base + 2 < NN) d_off[base + 2] = excl + c0 + c1;
    if (base + 3 < NN) d_off[base + 3] = excl + c0 + c1 + c2;
}

// Pass 2: exclusive scan of NSB (=49) block totals. One warp's worth of work.
__global__ void k_scan2() {
    int t = threadIdx.x;
    __shared__ int sh[64];
    sh[t] = (t < NSB) ? d_bsum[t] : 0;
    __syncthreads();
    int v = sh[t];
    int iv = v;
#pragma unroll
    for (int o = 1; o < 64; o <<= 1) {
        int x = (t >= o) ? sh[t - o] : 0;
        __syncthreads();
        sh[t] = iv = iv + x;
        __syncthreads();
    }
    if (t < NSB) d_bsum[t] = iv - v;      // exclusive base per block
}

// Pass 3: add block base, init d_pos, set sentinel.
__global__ void k_scan3() {
    int t = threadIdx.x;
    int base = blockIdx.x * SCAN_BLK + t * 4;
    int bb = d_bsum[blockIdx.x];
#pragma unroll
    for (int k = 0; k < 4; k++) {
        int i = base + k;
        if (i < NN) { int o = d_off[i] + bb; d_off[i] = o; d_pos[i] = o; }
    }
    if (blockIdx.x == 0 && t == 0) d_off[NN] = ETOT;
}

__global__ void k_scatter(const int* __restrict__ ei) {
    int i = blockIdx.x * blockDim.x + threadIdx.x;
    if (i >= ETOT) return;
    int s, d; edge_sd(ei, i, s, d);
    int p = atomicAdd(&d_pos[d], 1);
    d_csr_src[p] = s;
    d_csr_eid[p] = i;
}

// ---------------- per-layer compute ----------------
template <int CIN>
__global__ void k_gemm(const float* __restrict__ hin,
                       const float* __restrict__ W,
                       const float* __restrict__ as_,
                       const float* __restrict__ ad_) {
    const float* h = hin ? hin : d_h;
    int local = threadIdx.x >> 6;
    int j     = threadIdx.x & 63;
    int node  = blockIdx.x * 4 + local;

    __shared__ float sh[4][CIN];
    __shared__ float sred[8][2];

    for (int k = j; k < CIN; k += 64) sh[local][k] = h[node * CIN + k];
    __syncthreads();

    float acc = 0.f;
#pragma unroll
    for (int k = 0; k < CIN; k++) acc = fmaf(sh[local][k], W[k * C + j], acc);
    d_z[node * C + j] = acc;

    float ps = acc * as_[j];
    float pd = acc * ad_[j];
#pragma unroll
    for (int off = 16; off; off >>= 1) {
        ps += __shfl_down_sync(0xffffffffu, ps, off);
        pd += __shfl_down_sync(0xffffffffu, pd, off);
    }
    int w = threadIdx.x >> 5;
    if ((threadIdx.x & 31) == 0) { sred[w][0] = ps; sred[w][1] = pd; }
    __syncthreads();
    if (j == 0) {
        d_es[node] = sred[2 * local][0] + sred[2 * local + 1][0];
        d_ed[node] = sred[2 * local][1] + sred[2 * local + 1][1];
    }
}

// Warp per dst node: segment max -> exp-sum -> alpha-weighted gather of z.
template <int WRITE_OUT>
__global__ void k_node(const float* __restrict__ b,
                       float* __restrict__ outh,
                       float* __restrict__ out_alpha) {
    int w = (blockIdx.x * blockDim.x + threadIdx.x) >> 5;
    if (w >= NN) return;
    int lane = threadIdx.x & 31;
    int beg = d_off[w], end = d_off[w + 1];
    float edv = d_ed[w];

    float m = -1e30f;
    for (int e = beg + lane; e < end; e += 32) {
        float v = d_es[d_csr_src[e]] + edv;
        v = v > 0.f ? v : 0.2f * v;
        m = fmaxf(m, v);
    }
#pragma unroll
    for (int o = 16; o; o >>= 1) m = fmaxf(m, __shfl_xor_sync(0xffffffffu, m, o));

    float den = 0.f;
    for (int e = beg + lane; e < end; e += 32) {
        float v = d_es[d_csr_src[e]] + edv;
        v = v > 0.f ? v : 0.2f * v;
        den += __expf(v - m);
    }
#pragma unroll
    for (int o = 16; o; o >>= 1) den += __shfl_xor_sync(0xffffffffu, den, o);
    float inv = 1.f / (den + 1e-16f);

    float a0 = 0.f, a1 = 0.f;
    for (int e = beg; e < end; e++) {
        int s = d_csr_src[e];
        float v = d_es[s] + edv;
        v = v > 0.f ? v : 0.2f * v;
        float alpha = __expf(v - m) * inv;
        a0 = fmaf(alpha, d_z[s * C + lane], a0);
        a1 = fmaf(alpha, d_z[s * C + 32 + lane], a1);
        if (WRITE_OUT && lane == 0) out_alpha[d_csr_eid[e]] = alpha;
    }
    float o0 = a0 + b[lane];      o0 = o0 > 0.f ? o0 : 0.01f * o0;
    float o1 = a1 + b[lane + 32]; o1 = o1 > 0.f ? o1 : 0.01f * o1;
    if (WRITE_OUT) { outh[w * C + lane] = o0; outh[w * C + 32 + lane] = o1; }
    else           { d_h[w * C + lane] = o0;  d_h[w * C + 32 + lane] = o1; }
}

// ei output region: [2, E+N] row-major, cast to float
__global__ void k_write_ei(const int* __restrict__ ei,
                           float* __restrict__ out) {
    int t = blockIdx.x * blockDim.x + threadIdx.x;
    if (t >= 2 * ETOT) return;
    int row = t / ETOT, k = t - row * ETOT;
    int v = (k < NE) ? ei[row * NE + k] : (k - NE);
    out[t] = (float)v;
}

extern "C" void kernel_launch(void* const* d_in, const int* in_sizes, int n_in,
                              void* d_out, int out_size) {
    const float* x  = (const float*)d_in[0];
    const int*   ei = (const int*)d_in[1];
    const float* W[3]   = {(const float*)d_in[2], (const float*)d_in[6],  (const float*)d_in[10]};
    const float* as_[3] = {(const float*)d_in[3], (const float*)d_in[7],  (const float*)d_in[11]};
    const float* ad_[3] = {(const float*)d_in[4], (const float*)d_in[8],  (const float*)d_in[12]};
    const float* b[3]   = {(const float*)d_in[5], (const float*)d_in[9],  (const float*)d_in[13]};

    float* out       = (float*)d_out;
    bool   tuple_out = (out_size > NN * C);
    float* out_ei    = tuple_out ? out + NN * C : nullptr;
    float* out_alpha = tuple_out ? out + NN * C + 2 * ETOT : nullptr;

    if (tuple_out)
        k_write_ei<<<(2 * ETOT + 255) / 256, 256>>>(ei, out_ei);

    // CSR build (once per launch)
    k_zero_cnt<<<(NN + 255) / 256, 256>>>();
    k_hist<<<(ETOT + 255) / 256, 256>>>(ei);
    k_scan1<<<NSB, 256>>>();
    k_scan2<<<1, 64>>>();
    k_scan3<<<NSB, 256>>>();
    k_scatter<<<(ETOT + 255) / 256, 256>>>(ei);

    for (int l = 0; l < 3; l++) {
        if (l == 0) k_gemm<128><<<NN / 4, 256>>>(x, W[0], as_[0], ad_[0]);
        else        k_gemm<64><<<NN / 4, 256>>>(nullptr, W[l], as_[l], ad_[l]);
        if (l == 2) k_node<1><<<(NN * 32 + 255) / 256, 256>>>(b[l], out, out_alpha);
        else        k_node<0><<<(NN * 32 + 255) / 256, 256>>>(b[l], nullptr, nullptr);
    }
}

// round 6
// speedup vs baseline: 2.2954x; 1.1294x over previous
#include <cuda_runtime.h>

#define NN 50000
#define NE 800000
#define ETOT (NE + NN)   // 850000 edges incl. self loops
#define C 64

#define SCAN_BLK 1024
#define NSB ((NN + SCAN_BLK - 1) / SCAN_BLK)  // 49

// ---------------- scratch (no allocations allowed) ----------------
__device__ __align__(16) float d_z[NN * C];
__device__ __align__(16) float d_h[NN * C];
__device__ float d_es[NN];
__device__ float d_ed[NN];
__device__ int d_cnt[NN];
__device__ int d_off[NN + 1];
__device__ int d_pos[NN];
__device__ int d_bsum[NSB];
__device__ int d_csr_src[ETOT];
__device__ int d_csr_eid[ETOT];

__device__ __forceinline__ void edge_sd(const int* __restrict__ ei,
                                        int i, int& s, int& d) {
    if (i < NE) { s = ei[i]; d = ei[NE + i]; }
    else        { s = i - NE; d = s; }
}

// ---------------- CSR build ----------------
__global__ void k_zero_cnt() {
    int t = blockIdx.x * blockDim.x + threadIdx.x;
    if (t < NN) d_cnt[t] = 0;
}

__global__ void k_hist(const int* __restrict__ ei) {
    int i = blockIdx.x * blockDim.x + threadIdx.x;
    if (i >= ETOT) return;
    int s, d; edge_sd(ei, i, s, d);
    atomicAdd(&d_cnt[d], 1);
}

__global__ void k_scan1() {
    int t = threadIdx.x, lane = t & 31, warp = t >> 5;
    int base = blockIdx.x * SCAN_BLK + t * 4;
    int c0 = (base + 0 < NN) ? d_cnt[base + 0] : 0;
    int c1 = (base + 1 < NN) ? d_cnt[base + 1] : 0;
    int c2 = (base + 2 < NN) ? d_cnt[base + 2] : 0;
    int c3 = (base + 3 < NN) ? d_cnt[base + 3] : 0;
    int s = c0 + c1 + c2 + c3;

    int inc = s;
#pragma unroll
    for (int o = 1; o < 32; o <<= 1) {
        int x = __shfl_up_sync(0xffffffffu, inc, o);
        if (lane >= o) inc += x;
    }
    __shared__ int wsum[8];
    if (lane == 31) wsum[warp] = inc;
    __syncthreads();
    if (t < 8) {
        int x = wsum[t];
        int ix = x;
#pragma unroll
        for (int o = 1; o < 8; o <<= 1) {
            int y = __shfl_up_sync(0xffu, ix, o);
            if (t >= o) ix += y;
        }
        wsum[t] = ix - x;
        if (t == 7) d_bsum[blockIdx.x] = ix;
    }
    __syncthreads();
    int excl = wsum[warp] + inc - s;
    if (base + 0 < NN) d_off[base + 0] = excl;
    if (base + 1 < NN) d_off[base + 1] = excl + c0;
    if (base + 2 < NN) d_off[base + 2] = excl + c0 + c1;
    if (base + 3 < NN) d_off[base + 3] = excl + c0 + c1 + c2;
}

__global__ void k_scan2() {
    int t = threadIdx.x;
    __shared__ int sh[64];
    sh[t] = (t < NSB) ? d_bsum[t] : 0;
    __syncthreads();
    int v = sh[t];
    int iv = v;
#pragma unroll
    for (int o = 1; o < 64; o <<= 1) {
        int x = (t >= o) ? sh[t - o] : 0;
        __syncthreads();
        sh[t] = iv = iv + x;
        __syncthreads();
    }
    if (t < NSB) d_bsum[t] = iv - v;
}

__global__ void k_scan3() {
    int t = threadIdx.x;
    int base = blockIdx.x * SCAN_BLK + t * 4;
    int bb = d_bsum[blockIdx.x];
#pragma unroll
    for (int k = 0; k < 4; k++) {
        int i = base + k;
        if (i < NN) { int o = d_off[i] + bb; d_off[i] = o; d_pos[i] = o; }
    }
    if (blockIdx.x == 0 && t == 0) d_off[NN] = ETOT;
}

__global__ void k_scatter(const int* __restrict__ ei) {
    int i = blockIdx.x * blockDim.x + threadIdx.x;
    if (i >= ETOT) return;
    int s, d; edge_sd(ei, i, s, d);
    int p = atomicAdd(&d_pos[d], 1);
    d_csr_src[p] = s;
    d_csr_eid[p] = i;
}

// ---------------- per-layer compute ----------------
// W staged in smem once per block; 16 nodes/block; thread = (node nl, 4-col group jg).
// Per k: 1 broadcast LDS (h) + 1 LDS.128 (W) + 4 FMA.
template <int CIN>
__global__ void __launch_bounds__(256) k_gemm(
        const float* __restrict__ hin,
        const float* __restrict__ W,
        const float* __restrict__ as_,
        const float* __restrict__ ad_) {
    const float* h = hin ? hin : d_h;
    int t  = threadIdx.x;
    int jg = t & 15;        // col group: cols 4jg..4jg+3
    int nl = t >> 4;        // node 0..15
    int node0 = blockIdx.x * 16;

    __shared__ __align__(16) float W_s[CIN * C];          // [k][j]
    __shared__ __align__(16) float h_s[16][CIN + 4];      // +4: dodge bank conflicts, keep 16B align

    {
        float4* Wd = (float4*)W_s;
        const float4* Ws = (const float4*)W;
#pragma unroll
        for (int i = t; i < CIN * C / 4; i += 256) Wd[i] = Ws[i];
        const float4* hs = (const float4*)h;
        for (int i = t; i < 16 * CIN / 4; i += 256) {
            int n = i / (CIN / 4), k4 = i % (CIN / 4);
            ((float4*)&h_s[n][0])[k4] = hs[(node0 + n) * (CIN / 4) + k4];
        }
    }
    __syncthreads();

    float4 acc = make_float4(0.f, 0.f, 0.f, 0.f);
    const float4* W4 = (const float4*)W_s;
#pragma unroll
    for (int k = 0; k < CIN; k++) {
        float hv = h_s[nl][k];
        float4 wv = W4[k * 16 + jg];
        acc.x = fmaf(hv, wv.x, acc.x);
        acc.y = fmaf(hv, wv.y, acc.y);
        acc.z = fmaf(hv, wv.z, acc.z);
        acc.w = fmaf(hv, wv.w, acc.w);
    }
    int node = node0 + nl;
    ((float4*)d_z)[node * 16 + jg] = acc;

    // es/ed: dot(z_row, a_src/a_dst), reduced across the 16 threads of this node
    float4 av = ((const float4*)as_)[jg];
    float4 dv = ((const float4*)ad_)[jg];
    float ps = acc.x * av.x + acc.y * av.y + acc.z * av.z + acc.w * av.w;
    float pd = acc.x * dv.x + acc.y * dv.y + acc.z * dv.z + acc.w * dv.w;
#pragma unroll
    for (int o = 8; o; o >>= 1) {
        ps += __shfl_down_sync(0xffffffffu, ps, o, 16);
        pd += __shfl_down_sync(0xffffffffu, pd, o, 16);
    }
    if (jg == 0) { d_es[node] = ps; d_ed[node] = pd; }
}

// Warp per dst node: segment max -> exp-sum -> alpha-weighted gather of z.
template <int WRITE_OUT>
__global__ void k_node(const float* __restrict__ b,
                       float* __restrict__ outh,
                       float* __restrict__ out_alpha) {
    int w = (blockIdx.x * blockDim.x + threadIdx.x) >> 5;
    if (w >= NN) return;
    int lane = threadIdx.x & 31;
    int beg = d_off[w], end = d_off[w + 1];
    float edv = d_ed[w];

    float m = -1e30f;
    for (int e = beg + lane; e < end; e += 32) {
        float v = d_es[d_csr_src[e]] + edv;
        v = v > 0.f ? v : 0.2f * v;
        m = fmaxf(m, v);
    }
#pragma unroll
    for (int o = 16; o; o >>= 1) m = fmaxf(m, __shfl_xor_sync(0xffffffffu, m, o));

    float den = 0.f;
    for (int e = beg + lane; e < end; e += 32) {
        float v = d_es[d_csr_src[e]] + edv;
        v = v > 0.f ? v : 0.2f * v;
        den += __expf(v - m);
    }
#pragma unroll
    for (int o = 16; o; o >>= 1) den += __shfl_xor_sync(0xffffffffu, den, o);
    float inv = 1.f / (den + 1e-16f);

    float a0 = 0.f, a1 = 0.f;
    for (int e = beg; e < end; e++) {
        int s = d_csr_src[e];
        float v = d_es[s] + edv;
        v = v > 0.f ? v : 0.2f * v;
        float alpha = __expf(v - m) * inv;
        a0 = fmaf(alpha, d_z[s * C + lane], a0);
        a1 = fmaf(alpha, d_z[s * C + 32 + lane], a1);
        if (WRITE_OUT && lane == 0) out_alpha[d_csr_eid[e]] = alpha;
    }
    float o0 = a0 + b[lane];      o0 = o0 > 0.f ? o0 : 0.01f * o0;
    float o1 = a1 + b[lane + 32]; o1 = o1 > 0.f ? o1 : 0.01f * o1;
    if (WRITE_OUT) { outh[w * C + lane] = o0; outh[w * C + 32 + lane] = o1; }
    else           { d_h[w * C + lane] = o0;  d_h[w * C + 32 + lane] = o1; }
}

// ei output region: [2, E+N] row-major, cast to float
__global__ void k_write_ei(const int* __restrict__ ei,
                           float* __restrict__ out) {
    int t = blockIdx.x * blockDim.x + threadIdx.x;
    if (t >= 2 * ETOT) return;
    int row = t / ETOT, k = t - row * ETOT;
    int v = (k < NE) ? ei[row * NE + k] : (k - NE);
    out[t] = (float)v;
}

extern "C" void kernel_launch(void* const* d_in, const int* in_sizes, int n_in,
                              void* d_out, int out_size) {
    const float* x  = (const float*)d_in[0];
    const int*   ei = (const int*)d_in[1];
    const float* W[3]   = {(const float*)d_in[2], (const float*)d_in[6],  (const float*)d_in[10]};
    const float* as_[3] = {(const float*)d_in[3], (const float*)d_in[7],  (const float*)d_in[11]};
    const float* ad_[3] = {(const float*)d_in[4], (const float*)d_in[8],  (const float*)d_in[12]};
    const float* b[3]   = {(const float*)d_in[5], (const float*)d_in[9],  (const float*)d_in[13]};

    float* out       = (float*)d_out;
    bool   tuple_out = (out_size > NN * C);
    float* out_ei    = tuple_out ? out + NN * C : nullptr;
    float* out_alpha = tuple_out ? out + NN * C + 2 * ETOT : nullptr;

    if (tuple_out)
        k_write_ei<<<(2 * ETOT + 255) / 256, 256>>>(ei, out_ei);

    k_zero_cnt<<<(NN + 255) / 256, 256>>>();
    k_hist<<<(ETOT + 255) / 256, 256>>>(ei);
    k_scan1<<<NSB, 256>>>();
    k_scan2<<<1, 64>>>();
    k_scan3<<<NSB, 256>>>();
    k_scatter<<<(ETOT + 255) / 256, 256>>>(ei);

    // NN = 50000 = 3125 * 16
    for (int l = 0; l < 3; l++) {
        if (l == 0) k_gemm<128><<<NN / 16, 256>>>(x, W[0], as_[0], ad_[0]);
        else        k_gemm<64><<<NN / 16, 256>>>(nullptr, W[l], as_[l], ad_[l]);
        if (l == 2) k_node<1><<<(NN * 32 + 255) / 256, 256>>>(b[l], out, out_alpha);
        else        k_node<0><<<(NN * 32 + 255) / 256, 256>>>(b[l], nullptr, nullptr);
    }
}